// round 3
// baseline (speedup 1.0000x reference)
#include <cuda_runtime.h>
#include <math.h>

// ---------------------------------------------------------------------------
// ConvLSTM (2 layers, 12 steps) on GB300 — FFMA2 kernel, ALU-lean v2.
// Layer0: Cin=129 (x:1 + h0:128), hid=128  -> conv channels 512
// Layer1: Cin=140 (h0:128 + h1:12), hid=12 -> conv channels 48
// Gate order along conv-channel axis: [i | f | o | g], each of size hid.
// c_next = sig(f)*c + sig(i)*tanh(g);  h_next = sig(o)*tanh(c_next)
//
// Key idea this round: dual-parity input rows in smem (rowE[i]=v(i-1),
// rowO[i]=v(i)) so ALL conv operand pairs are aligned LDS.64 — zero
// register-pair packing MOVs in the inner loop. Thread = 8px x 1hid x 4gates.
// ---------------------------------------------------------------------------

#define HW     4096
#define TSTEPS 12

// -------------------- device scratch (no allocations allowed) --------------
__device__ float g_h0[2u * 16u * 128u * 4096u];   // ping-pong h layer0
__device__ float g_c0[16u * 128u * 4096u];        // c layer0 (in-place)
__device__ float g_h1[2u * 16u * 12u * 4096u];    // ping-pong h layer1
__device__ float g_c1[16u * 12u * 4096u];
__device__ float g_wp0[64u * 136u * 9u * 16u];    // repacked+dup weights L0
__device__ float g_wp1[6u  * 144u * 9u * 16u];    // repacked+dup weights L1

// -------------------- helpers: packed f32x2 --------------------------------
__device__ __forceinline__ void fma2(unsigned long long& d,
                                     unsigned long long a,
                                     unsigned long long b) {
    asm("fma.rn.f32x2 %0, %1, %2, %0;" : "+l"(d) : "l"(a), "l"(b));
}
__device__ __forceinline__ float2 up2(unsigned long long v) {
    float2 f;
    asm("mov.b64 {%0,%1}, %2;" : "=f"(f.x), "=f"(f.y) : "l"(v));
    return f;
}
__device__ __forceinline__ float sigf(float x) {
    return 1.0f / (1.0f + __expf(-x));
}

// -------------------- init / repack ----------------------------------------
__global__ void zero_init_kernel() {
    size_t tid = (size_t)blockIdx.x * blockDim.x + threadIdx.x;
    size_t stride = (size_t)gridDim.x * blockDim.x;
    const size_t n0 = (size_t)16 * 128 * 4096;
    const size_t n1 = (size_t)16 * 12 * 4096;
    for (size_t i = tid; i < n0; i += stride) { g_h0[i] = 0.f; g_c0[i] = 0.f; }
    for (size_t i = tid; i < n1; i += stride) { g_h1[i] = 0.f; g_c1[i] = 0.f; }
}

// Repack W[(4*HID), CIN, 3, 3] -> Wp[hb(HID/2)][cinp][tap(9)][hl(2)][g(4)][dup(2)]
// Each weight duplicated into both f32x2 halves (no packs in inner loop).
__global__ void repack_kernel(const float* __restrict__ W, float* __restrict__ Wp,
                              int HID, int CIN, int CINP) {
    int total = (HID / 2) * CINP * 9 * 16;
    for (int idx = blockIdx.x * blockDim.x + threadIdx.x; idx < total;
         idx += gridDim.x * blockDim.x) {
        int g   = (idx >> 1) & 3;
        int hl  = (idx >> 3) & 1;
        int t   = idx >> 4;          // ((hb*CINP + cin)*9 + tap)
        int tap = t % 9;
        int ci  = t / 9;
        int cin = ci % CINP;
        int hb  = ci / CINP;
        int hid = hb * 2 + hl;
        float v = 0.f;
        if (cin < CIN) v = W[((size_t)(g * HID + hid) * CIN + cin) * 9 + tap];
        Wp[idx] = v;
    }
}

// -------------------- fused conv + LSTM gate step ---------------------------
// Block: 128 threads = (tx:8)x(ty:8)x(tz:2). Tile = full-width 64 x 8 rows.
// Block covers 2 hid channels (tz = which). Thread: 8 px x 1 hid x 4 gates
// = 16 f32x2 accumulators.
// Smem per ck,row: rowE[68] (v shifted +1) + pad + rowO[68] (v), stride 144.
template <int CINP, int CIN, int CA, int HID>
__global__ __launch_bounds__(128)
void convlstm_step(const float* __restrict__ srcA, int bstrA,
                   const float* __restrict__ srcB,
                   const float* __restrict__ Wp,
                   const float* __restrict__ bias,
                   float* __restrict__ cbuf,
                   float* __restrict__ hout) {
    __shared__ __align__(16) float sm[4 * 1440 + 576];
    float* in_s = sm;                 // 4 ck x 10 rows x 144 (rowE@0, rowO@72)
    float* w_s  = sm + 4 * 1440;      // 4 ck x 9 taps x 2 hl x 4 g x 2 dup

    const int tid = threadIdx.x;
    const int tx  = tid & 7;          // 8 px each -> 64 wide
    const int ty  = (tid >> 3) & 7;   // 8 rows
    const int tz  = tid >> 6;         // which of 2 hid

    const int y0 = blockIdx.x * 8;
    const int hb = blockIdx.y;
    const int b  = blockIdx.z;

    const float* baseA = srcA + (size_t)b * bstrA;
    const float* baseB = srcB + (size_t)b * (CIN - CA) * HW;
    const float4* wsrc_base = (const float4*)(Wp + (size_t)hb * CINP * 9 * 16);

    // Zero the rowE entries the loader never writes (rowE[0], rowE[65]).
    for (int idx = tid; idx < 40; idx += 128) {
        int ck = idx / 10, r = idx - ck * 10;
        float* rb = in_s + ck * 1440 + r * 144;
        rb[0] = 0.f;
        rb[65] = 0.f;
    }

    unsigned long long acc[4][4];
#pragma unroll
    for (int g = 0; g < 4; g++)
#pragma unroll
        for (int j = 0; j < 4; j++) acc[g][j] = 0ull;

    const int lslot = tid >> 4;        // 0..7  (row-unit slot)
    const int lxv   = (tid & 15) * 4;  // 0..60 (x of float4)

    float4 pre[5];
    float4 wpre0, wpre1;

    auto ldg_chunk = [&](int ch) {
#pragma unroll
        for (int it = 0; it < 5; it++) {
            int u   = lslot + it * 8;        // 0..39 = ck*10 + r
            int ck  = u / 10;
            int r   = u - ck * 10;
            int cin = ch * 4 + ck;
            int gy  = y0 + r - 1;
            float4 v = make_float4(0.f, 0.f, 0.f, 0.f);
            if (cin < CIN && (unsigned)gy < 64u) {
                const float* p = (cin < CA)
                    ? baseA + (size_t)cin * HW + gy * 64 + lxv
                    : baseB + (size_t)(cin - CA) * HW + gy * 64 + lxv;
                v = *(const float4*)p;
            }
            pre[it] = v;
        }
        const float4* ws = wsrc_base + ch * 144;
        wpre0 = ws[tid];
        wpre1 = (tid < 16) ? ws[128 + tid] : make_float4(0.f, 0.f, 0.f, 0.f);
    };

    auto sts_chunk = [&]() {
#pragma unroll
        for (int it = 0; it < 5; it++) {
            int u  = lslot + it * 8;
            int ck = u / 10;
            int r  = u - ck * 10;
            float* rb = in_s + ck * 1440 + r * 144;
            float4 v = pre[it];
            *(float4*)(rb + 72 + lxv) = v;                    // rowO[x..x+3]
            rb[lxv + 1] = v.x;                                // rowE[x+1]
            *(float2*)(rb + lxv + 2) = make_float2(v.y, v.z); // rowE[x+2..3]
            rb[lxv + 4] = v.w;                                // rowE[x+4]
        }
        ((float4*)w_s)[tid] = wpre0;
        if (tid < 16) ((float4*)w_s)[128 + tid] = wpre1;
    };

    ldg_chunk(0);
    const int NCH = CINP / 4;
    const int X2  = tx * 4;            // (x-start)/2 in pair units

    for (int ch = 0; ch < NCH; ch++) {
        __syncthreads();
        sts_chunk();
        __syncthreads();
        if (ch + 1 < NCH) ldg_chunk(ch + 1);

#pragma unroll
        for (int ck = 0; ck < 4; ck++) {
#pragma unroll
            for (int ky = 0; ky < 3; ky++) {
                const float* rb = in_s + ck * 1440 + (ty + ky) * 144;
                const unsigned long long* pe = (const unsigned long long*)rb;
                const unsigned long long* po = (const unsigned long long*)(rb + 72);
                unsigned long long e0 = pe[X2],     e1 = pe[X2 + 1],
                                   e2 = pe[X2 + 2], e3 = pe[X2 + 3],
                                   e4 = pe[X2 + 4];
                unsigned long long o0 = po[X2],     o1 = po[X2 + 1],
                                   o2 = po[X2 + 2], o3 = po[X2 + 3];
#pragma unroll
                for (int kx = 0; kx < 3; kx++) {
                    const float* wp = w_s + ((ck * 9 + ky * 3 + kx) * 2 + tz) * 8;
                    ulonglong2 wa = *(const ulonglong2*)wp;        // g0,g1 dup'd
                    ulonglong2 wb = *(const ulonglong2*)(wp + 4);  // g2,g3 dup'd
                    unsigned long long p0, p1, p2, p3;
                    if (kx == 0)      { p0 = e0; p1 = e1; p2 = e2; p3 = e3; } // x-1
                    else if (kx == 1) { p0 = o0; p1 = o1; p2 = o2; p3 = o3; } // x
                    else              { p0 = e1; p1 = e2; p2 = e3; p3 = e4; } // x+1
                    fma2(acc[0][0], p0, wa.x); fma2(acc[0][1], p1, wa.x);
                    fma2(acc[0][2], p2, wa.x); fma2(acc[0][3], p3, wa.x);
                    fma2(acc[1][0], p0, wa.y); fma2(acc[1][1], p1, wa.y);
                    fma2(acc[1][2], p2, wa.y); fma2(acc[1][3], p3, wa.y);
                    fma2(acc[2][0], p0, wb.x); fma2(acc[2][1], p1, wb.x);
                    fma2(acc[2][2], p2, wb.x); fma2(acc[2][3], p3, wb.x);
                    fma2(acc[3][0], p0, wb.y); fma2(acc[3][1], p1, wb.y);
                    fma2(acc[3][2], p2, wb.y); fma2(acc[3][3], p3, wb.y);
                }
            }
        }
    }

    // ---- epilogue: gates + state update (8 px, 1 hid)
    const int hid = hb * 2 + tz;
    const float bi = bias[0 * HID + hid];
    const float bf = bias[1 * HID + hid];
    const float bo = bias[2 * HID + hid];
    const float bg = bias[3 * HID + hid];

    const int y = y0 + ty;
    const size_t base = ((size_t)(b * HID + hid)) * HW + y * 64 + tx * 8;

    float4 cA = *(const float4*)(cbuf + base);
    float4 cB = *(const float4*)(cbuf + base + 4);
    float co[8] = {cA.x, cA.y, cA.z, cA.w, cB.x, cB.y, cB.z, cB.w};
    float cn[8], hn[8];

#pragma unroll
    for (int j = 0; j < 4; j++) {
        float2 fi = up2(acc[0][j]);
        float2 ff = up2(acc[1][j]);
        float2 fo = up2(acc[2][j]);
        float2 fg = up2(acc[3][j]);
        float iv[2] = {fi.x, fi.y};
        float fv[2] = {ff.x, ff.y};
        float ov[2] = {fo.x, fo.y};
        float gv[2] = {fg.x, fg.y};
#pragma unroll
        for (int q = 0; q < 2; q++) {
            int p = j * 2 + q;
            float I = sigf(iv[q] + bi);
            float F = sigf(fv[q] + bf);
            float O = sigf(ov[q] + bo);
            float G = tanhf(gv[q] + bg);
            float c_new = F * co[p] + I * G;
            cn[p] = c_new;
            hn[p] = O * tanhf(c_new);
        }
    }
    *(float4*)(cbuf + base)     = make_float4(cn[0], cn[1], cn[2], cn[3]);
    *(float4*)(cbuf + base + 4) = make_float4(cn[4], cn[5], cn[6], cn[7]);
    *(float4*)(hout + base)     = make_float4(hn[0], hn[1], hn[2], hn[3]);
    *(float4*)(hout + base + 4) = make_float4(hn[4], hn[5], hn[6], hn[7]);
}

// -------------------- host driver -------------------------------------------
extern "C" void kernel_launch(void* const* d_in, const int* in_sizes, int n_in,
                              void* d_out, int out_size) {
    (void)in_sizes; (void)n_in; (void)out_size;
    const float* history = (const float*)d_in[0];
    const float* W0 = (const float*)d_in[2];
    const float* b0 = (const float*)d_in[3];
    const float* W1 = (const float*)d_in[4];
    const float* b1 = (const float*)d_in[5];

    float *h0, *c0, *h1, *c1, *wp0, *wp1;
    cudaGetSymbolAddress((void**)&h0,  g_h0);
    cudaGetSymbolAddress((void**)&c0,  g_c0);
    cudaGetSymbolAddress((void**)&h1,  g_h1);
    cudaGetSymbolAddress((void**)&c1,  g_c1);
    cudaGetSymbolAddress((void**)&wp0, g_wp0);
    cudaGetSymbolAddress((void**)&wp1, g_wp1);

    zero_init_kernel<<<1024, 256>>>();
    repack_kernel<<<512, 256>>>(W0, wp0, 128, 129, 136);
    repack_kernel<<<64, 256>>>(W1, wp1, 12, 140, 144);

    const size_t H0SZ = (size_t)16 * 128 * 4096;
    const size_t H1SZ = (size_t)16 * 12 * 4096;

    int pa = 0;
    for (int t = 0; t < TSTEPS; t++) {
        const float* h0r = h0 + (size_t)pa * H0SZ;
        float*       h0w = h0 + (size_t)(1 - pa) * H0SZ;
        const float* h1r = h1 + (size_t)pa * H1SZ;
        float*       h1w = h1 + (size_t)(1 - pa) * H1SZ;

        // Layer 0: x_t (1ch) + h0 (128ch) -> hid 128
        convlstm_step<136, 129, 1, 128><<<dim3(8, 64, 16), 128>>>(
            history + (size_t)t * HW, TSTEPS * HW, h0r, wp0, b0, c0, h0w);

        // Layer 1: h0_cur (128ch) + h1 (12ch) -> hid 12
        convlstm_step<144, 140, 128, 12><<<dim3(8, 6, 16), 128>>>(
            h0w, 128 * HW, h1r, wp1, b1, c1, h1w);

        pa ^= 1;
    }

    // Final h of layer1 (12 steps -> buffer 0): layout (B, 12, 4096) == output.
    cudaMemcpyAsync(d_out, h1, H1SZ * sizeof(float), cudaMemcpyDeviceToDevice);
}

// round 4
// speedup vs baseline: 1.0012x; 1.0012x over previous
#include <cuda_runtime.h>
#include <math.h>

// ---------------------------------------------------------------------------
// ConvLSTM (2 layers, 12 steps) on GB300 — FFMA2 kernel, ALU-lean v2.
// Layer0: Cin=129 (x:1 + h0:128), hid=128  -> conv channels 512
// Layer1: Cin=140 (h0:128 + h1:12), hid=12 -> conv channels 48
// Gate order along conv-channel axis: [i | f | o | g], each of size hid.
// c_next = sig(f)*c + sig(i)*tanh(g);  h_next = sig(o)*tanh(c_next)
//
// Key idea this round: dual-parity input rows in smem (rowE[i]=v(i-1),
// rowO[i]=v(i)) so ALL conv operand pairs are aligned LDS.64 — zero
// register-pair packing MOVs in the inner loop. Thread = 8px x 1hid x 4gates.
// ---------------------------------------------------------------------------

#define HW     4096
#define TSTEPS 12

// -------------------- device scratch (no allocations allowed) --------------
__device__ float g_h0[2u * 16u * 128u * 4096u];   // ping-pong h layer0
__device__ float g_c0[16u * 128u * 4096u];        // c layer0 (in-place)
__device__ float g_h1[2u * 16u * 12u * 4096u];    // ping-pong h layer1
__device__ float g_c1[16u * 12u * 4096u];
__device__ float g_wp0[64u * 136u * 9u * 16u];    // repacked+dup weights L0
__device__ float g_wp1[6u  * 144u * 9u * 16u];    // repacked+dup weights L1

// -------------------- helpers: packed f32x2 --------------------------------
__device__ __forceinline__ void fma2(unsigned long long& d,
                                     unsigned long long a,
                                     unsigned long long b) {
    asm("fma.rn.f32x2 %0, %1, %2, %0;" : "+l"(d) : "l"(a), "l"(b));
}
__device__ __forceinline__ float2 up2(unsigned long long v) {
    float2 f;
    asm("mov.b64 {%0,%1}, %2;" : "=f"(f.x), "=f"(f.y) : "l"(v));
    return f;
}
__device__ __forceinline__ float sigf(float x) {
    return 1.0f / (1.0f + __expf(-x));
}

// -------------------- init / repack ----------------------------------------
__global__ void zero_init_kernel() {
    size_t tid = (size_t)blockIdx.x * blockDim.x + threadIdx.x;
    size_t stride = (size_t)gridDim.x * blockDim.x;
    const size_t n0 = (size_t)16 * 128 * 4096;
    const size_t n1 = (size_t)16 * 12 * 4096;
    for (size_t i = tid; i < n0; i += stride) { g_h0[i] = 0.f; g_c0[i] = 0.f; }
    for (size_t i = tid; i < n1; i += stride) { g_h1[i] = 0.f; g_c1[i] = 0.f; }
}

// Repack W[(4*HID), CIN, 3, 3] -> Wp[hb(HID/2)][cinp][tap(9)][hl(2)][g(4)][dup(2)]
// Each weight duplicated into both f32x2 halves (no packs in inner loop).
__global__ void repack_kernel(const float* __restrict__ W, float* __restrict__ Wp,
                              int HID, int CIN, int CINP) {
    int total = (HID / 2) * CINP * 9 * 16;
    for (int idx = blockIdx.x * blockDim.x + threadIdx.x; idx < total;
         idx += gridDim.x * blockDim.x) {
        int g   = (idx >> 1) & 3;
        int hl  = (idx >> 3) & 1;
        int t   = idx >> 4;          // ((hb*CINP + cin)*9 + tap)
        int tap = t % 9;
        int ci  = t / 9;
        int cin = ci % CINP;
        int hb  = ci / CINP;
        int hid = hb * 2 + hl;
        float v = 0.f;
        if (cin < CIN) v = W[((size_t)(g * HID + hid) * CIN + cin) * 9 + tap];
        Wp[idx] = v;
    }
}

// -------------------- fused conv + LSTM gate step ---------------------------
// Block: 128 threads = (tx:8)x(ty:8)x(tz:2). Tile = full-width 64 x 8 rows.
// Block covers 2 hid channels (tz = which). Thread: 8 px x 1 hid x 4 gates
// = 16 f32x2 accumulators.
// Smem per ck,row: rowE[68] (v shifted +1) + pad + rowO[68] (v), stride 144.
template <int CINP, int CIN, int CA, int HID>
__global__ __launch_bounds__(128)
void convlstm_step(const float* __restrict__ srcA, int bstrA,
                   const float* __restrict__ srcB,
                   const float* __restrict__ Wp,
                   const float* __restrict__ bias,
                   float* __restrict__ cbuf,
                   float* __restrict__ hout) {
    __shared__ __align__(16) float sm[4 * 1440 + 576];
    float* in_s = sm;                 // 4 ck x 10 rows x 144 (rowE@0, rowO@72)
    float* w_s  = sm + 4 * 1440;      // 4 ck x 9 taps x 2 hl x 4 g x 2 dup

    const int tid = threadIdx.x;
    const int tx  = tid & 7;          // 8 px each -> 64 wide
    const int ty  = (tid >> 3) & 7;   // 8 rows
    const int tz  = tid >> 6;         // which of 2 hid

    const int y0 = blockIdx.x * 8;
    const int hb = blockIdx.y;
    const int b  = blockIdx.z;

    const float* baseA = srcA + (size_t)b * bstrA;
    const float* baseB = srcB + (size_t)b * (CIN - CA) * HW;
    const float4* wsrc_base = (const float4*)(Wp + (size_t)hb * CINP * 9 * 16);

    // Zero the rowE entries the loader never writes (rowE[0], rowE[65]).
    for (int idx = tid; idx < 40; idx += 128) {
        int ck = idx / 10, r = idx - ck * 10;
        float* rb = in_s + ck * 1440 + r * 144;
        rb[0] = 0.f;
        rb[65] = 0.f;
    }

    unsigned long long acc[4][4];
#pragma unroll
    for (int g = 0; g < 4; g++)
#pragma unroll
        for (int j = 0; j < 4; j++) acc[g][j] = 0ull;

    const int lslot = tid >> 4;        // 0..7  (row-unit slot)
    const int lxv   = (tid & 15) * 4;  // 0..60 (x of float4)

    float4 pre[5];
    float4 wpre0, wpre1;

    auto ldg_chunk = [&](int ch) {
#pragma unroll
        for (int it = 0; it < 5; it++) {
            int u   = lslot + it * 8;        // 0..39 = ck*10 + r
            int ck  = u / 10;
            int r   = u - ck * 10;
            int cin = ch * 4 + ck;
            int gy  = y0 + r - 1;
            float4 v = make_float4(0.f, 0.f, 0.f, 0.f);
            if (cin < CIN && (unsigned)gy < 64u) {
                const float* p = (cin < CA)
                    ? baseA + (size_t)cin * HW + gy * 64 + lxv
                    : baseB + (size_t)(cin - CA) * HW + gy * 64 + lxv;
                v = *(const float4*)p;
            }
            pre[it] = v;
        }
        const float4* ws = wsrc_base + ch * 144;
        wpre0 = ws[tid];
        wpre1 = (tid < 16) ? ws[128 + tid] : make_float4(0.f, 0.f, 0.f, 0.f);
    };

    auto sts_chunk = [&]() {
#pragma unroll
        for (int it = 0; it < 5; it++) {
            int u  = lslot + it * 8;
            int ck = u / 10;
            int r  = u - ck * 10;
            float* rb = in_s + ck * 1440 + r * 144;
            float4 v = pre[it];
            *(float4*)(rb + 72 + lxv) = v;                    // rowO[x..x+3]
            rb[lxv + 1] = v.x;                                // rowE[x+1]
            *(float2*)(rb + lxv + 2) = make_float2(v.y, v.z); // rowE[x+2..3]
            rb[lxv + 4] = v.w;                                // rowE[x+4]
        }
        ((float4*)w_s)[tid] = wpre0;
        if (tid < 16) ((float4*)w_s)[128 + tid] = wpre1;
    };

    ldg_chunk(0);
    const int NCH = CINP / 4;
    const int X2  = tx * 4;            // (x-start)/2 in pair units

    for (int ch = 0; ch < NCH; ch++) {
        __syncthreads();
        sts_chunk();
        __syncthreads();
        if (ch + 1 < NCH) ldg_chunk(ch + 1);

#pragma unroll
        for (int ck = 0; ck < 4; ck++) {
#pragma unroll
            for (int ky = 0; ky < 3; ky++) {
                const float* rb = in_s + ck * 1440 + (ty + ky) * 144;
                const unsigned long long* pe = (const unsigned long long*)rb;
                const unsigned long long* po = (const unsigned long long*)(rb + 72);
                unsigned long long e0 = pe[X2],     e1 = pe[X2 + 1],
                                   e2 = pe[X2 + 2], e3 = pe[X2 + 3],
                                   e4 = pe[X2 + 4];
                unsigned long long o0 = po[X2],     o1 = po[X2 + 1],
                                   o2 = po[X2 + 2], o3 = po[X2 + 3];
#pragma unroll
                for (int kx = 0; kx < 3; kx++) {
                    const float* wp = w_s + ((ck * 9 + ky * 3 + kx) * 2 + tz) * 8;
                    ulonglong2 wa = *(const ulonglong2*)wp;        // g0,g1 dup'd
                    ulonglong2 wb = *(const ulonglong2*)(wp + 4);  // g2,g3 dup'd
                    unsigned long long p0, p1, p2, p3;
                    if (kx == 0)      { p0 = e0; p1 = e1; p2 = e2; p3 = e3; } // x-1
                    else if (kx == 1) { p0 = o0; p1 = o1; p2 = o2; p3 = o3; } // x
                    else              { p0 = e1; p1 = e2; p2 = e3; p3 = e4; } // x+1
                    fma2(acc[0][0], p0, wa.x); fma2(acc[0][1], p1, wa.x);
                    fma2(acc[0][2], p2, wa.x); fma2(acc[0][3], p3, wa.x);
                    fma2(acc[1][0], p0, wa.y); fma2(acc[1][1], p1, wa.y);
                    fma2(acc[1][2], p2, wa.y); fma2(acc[1][3], p3, wa.y);
                    fma2(acc[2][0], p0, wb.x); fma2(acc[2][1], p1, wb.x);
                    fma2(acc[2][2], p2, wb.x); fma2(acc[2][3], p3, wb.x);
                    fma2(acc[3][0], p0, wb.y); fma2(acc[3][1], p1, wb.y);
                    fma2(acc[3][2], p2, wb.y); fma2(acc[3][3], p3, wb.y);
                }
            }
        }
    }

    // ---- epilogue: gates + state update (8 px, 1 hid)
    const int hid = hb * 2 + tz;
    const float bi = bias[0 * HID + hid];
    const float bf = bias[1 * HID + hid];
    const float bo = bias[2 * HID + hid];
    const float bg = bias[3 * HID + hid];

    const int y = y0 + ty;
    const size_t base = ((size_t)(b * HID + hid)) * HW + y * 64 + tx * 8;

    float4 cA = *(const float4*)(cbuf + base);
    float4 cB = *(const float4*)(cbuf + base + 4);
    float co[8] = {cA.x, cA.y, cA.z, cA.w, cB.x, cB.y, cB.z, cB.w};
    float cn[8], hn[8];

#pragma unroll
    for (int j = 0; j < 4; j++) {
        float2 fi = up2(acc[0][j]);
        float2 ff = up2(acc[1][j]);
        float2 fo = up2(acc[2][j]);
        float2 fg = up2(acc[3][j]);
        float iv[2] = {fi.x, fi.y};
        float fv[2] = {ff.x, ff.y};
        float ov[2] = {fo.x, fo.y};
        float gv[2] = {fg.x, fg.y};
#pragma unroll
        for (int q = 0; q < 2; q++) {
            int p = j * 2 + q;
            float I = sigf(iv[q] + bi);
            float F = sigf(fv[q] + bf);
            float O = sigf(ov[q] + bo);
            float G = tanhf(gv[q] + bg);
            float c_new = F * co[p] + I * G;
            cn[p] = c_new;
            hn[p] = O * tanhf(c_new);
        }
    }
    *(float4*)(cbuf + base)     = make_float4(cn[0], cn[1], cn[2], cn[3]);
    *(float4*)(cbuf + base + 4) = make_float4(cn[4], cn[5], cn[6], cn[7]);
    *(float4*)(hout + base)     = make_float4(hn[0], hn[1], hn[2], hn[3]);
    *(float4*)(hout + base + 4) = make_float4(hn[4], hn[5], hn[6], hn[7]);
}

// -------------------- host driver -------------------------------------------
extern "C" void kernel_launch(void* const* d_in, const int* in_sizes, int n_in,
                              void* d_out, int out_size) {
    (void)in_sizes; (void)n_in; (void)out_size;
    const float* history = (const float*)d_in[0];
    const float* W0 = (const float*)d_in[2];
    const float* b0 = (const float*)d_in[3];
    const float* W1 = (const float*)d_in[4];
    const float* b1 = (const float*)d_in[5];

    float *h0, *c0, *h1, *c1, *wp0, *wp1;
    cudaGetSymbolAddress((void**)&h0,  g_h0);
    cudaGetSymbolAddress((void**)&c0,  g_c0);
    cudaGetSymbolAddress((void**)&h1,  g_h1);
    cudaGetSymbolAddress((void**)&c1,  g_c1);
    cudaGetSymbolAddress((void**)&wp0, g_wp0);
    cudaGetSymbolAddress((void**)&wp1, g_wp1);

    zero_init_kernel<<<1024, 256>>>();
    repack_kernel<<<512, 256>>>(W0, wp0, 128, 129, 136);
    repack_kernel<<<64, 256>>>(W1, wp1, 12, 140, 144);

    const size_t H0SZ = (size_t)16 * 128 * 4096;
    const size_t H1SZ = (size_t)16 * 12 * 4096;

    int pa = 0;
    for (int t = 0; t < TSTEPS; t++) {
        const float* h0r = h0 + (size_t)pa * H0SZ;
        float*       h0w = h0 + (size_t)(1 - pa) * H0SZ;
        const float* h1r = h1 + (size_t)pa * H1SZ;
        float*       h1w = h1 + (size_t)(1 - pa) * H1SZ;

        // Layer 0: x_t (1ch) + h0 (128ch) -> hid 128
        convlstm_step<136, 129, 1, 128><<<dim3(8, 64, 16), 128>>>(
            history + (size_t)t * HW, TSTEPS * HW, h0r, wp0, b0, c0, h0w);

        // Layer 1: h0_cur (128ch) + h1 (12ch) -> hid 12
        convlstm_step<144, 140, 128, 12><<<dim3(8, 6, 16), 128>>>(
            h0w, 128 * HW, h1r, wp1, b1, c1, h1w);

        pa ^= 1;
    }

    // Final h of layer1 (12 steps -> buffer 0): layout (B, 12, 4096) == output.
    cudaMemcpyAsync(d_out, h1, H1SZ * sizeof(float), cudaMemcpyDeviceToDevice);
}

// round 5
// speedup vs baseline: 3.9644x; 3.9597x over previous
#include <cuda_runtime.h>
#include <cuda_bf16.h>
#include <math.h>
#include <stdint.h>

// ---------------------------------------------------------------------------
// ConvLSTM (2 layers, 12 steps) — tensor-core implicit GEMM, bf16 2-term split.
// Activations stored as channel-pair planes: uint32 = {bf16 ch2p | bf16 ch2p+1}.
// cin reordered: [h pairs][extra pairs]; weights repacked to match.
// ---------------------------------------------------------------------------

#define TSTEPS 12
#define NCHUNK 9

__device__ uint32_t g_h0p[2u * 16u * 64u * 2u * 4096u];  // h0 pair planes (hi,lo)
__device__ uint32_t g_h1p[2u * 16u * 6u  * 2u * 4096u];  // h1 pair planes
__device__ uint32_t g_xp [12u * 16u * 2u * 4096u];       // x pair planes per t
__device__ float    g_c0 [16u * 128u * 4096u];
__device__ float    g_c1 [16u * 12u  * 4096u];
__device__ float    g_h1f[16u * 12u * 4096u];            // float h1 (output)
__device__ uint32_t g_wp0[8u * 9u * 9216u];              // frag-packed weights
__device__ uint32_t g_wp1[1u * 9u * 9216u];

#define SW_ACT_S   5824u            // one split: 8 planes * 728 words
#define SW_ACT_BUF 11648u           // hi + lo
#define SW_W_OFF   23296u
#define SW_W_BUF   9216u
#define SMEM_BYTES ((23296u + 18432u) * 4u)   // 166,912 B

// -------------------- helpers ----------------------------------------------
__device__ __forceinline__ void mma_bf16(float* d, const uint32_t* a,
                                         uint32_t b0, uint32_t b1) {
    asm volatile(
        "mma.sync.aligned.m16n8k16.row.col.f32.bf16.bf16.f32 "
        "{%0,%1,%2,%3}, {%4,%5,%6,%7}, {%8,%9}, {%0,%1,%2,%3};"
        : "+f"(d[0]), "+f"(d[1]), "+f"(d[2]), "+f"(d[3])
        : "r"(a[0]), "r"(a[1]), "r"(a[2]), "r"(a[3]), "r"(b0), "r"(b1));
}
__device__ __forceinline__ uint32_t smaddr(const void* p) {
    return (uint32_t)__cvta_generic_to_shared(p);
}
__device__ __forceinline__ void cpa16(uint32_t dst, const void* src) {
    asm volatile("cp.async.cg.shared.global [%0], [%1], 16;" :: "r"(dst), "l"(src));
}
__device__ __forceinline__ uint32_t pack_bf(float a, float b) {
    return (uint32_t)__bfloat16_as_ushort(__float2bfloat16_rn(a)) |
           ((uint32_t)__bfloat16_as_ushort(__float2bfloat16_rn(b)) << 16);
}
__device__ __forceinline__ float bflo(float v) {
    return v - __bfloat162float(__float2bfloat16_rn(v));
}
__device__ __forceinline__ float sigf(float x) { return 1.f / (1.f + __expf(-x)); }

// -------------------- init kernels -----------------------------------------
__global__ void zero_init_kernel() {
    size_t tid = (size_t)blockIdx.x * blockDim.x + threadIdx.x;
    size_t st  = (size_t)gridDim.x * blockDim.x;
    const size_t nh0 = (size_t)2 * 16 * 64 * 2 * 4096;
    const size_t nh1 = (size_t)2 * 16 * 6 * 2 * 4096;
    const size_t nc0 = (size_t)16 * 128 * 4096;
    const size_t nc1 = (size_t)16 * 12 * 4096;
    for (size_t i = tid; i < nh0; i += st) g_h0p[i] = 0u;
    for (size_t i = tid; i < nh1; i += st) g_h1p[i] = 0u;
    for (size_t i = tid; i < nc0; i += st) g_c0[i] = 0.f;
    for (size_t i = tid; i < nc1; i += st) g_c1[i] = 0.f;
}

__global__ void xprep_kernel(const float* __restrict__ hist) {
    int n = TSTEPS * 16 * 4096;
    for (int i = blockIdx.x * blockDim.x + threadIdx.x; i < n;
         i += gridDim.x * blockDim.x) {
        int px = i & 4095, b = (i >> 12) & 15, t = i >> 16;
        float v = hist[((size_t)b * TSTEPS + t) * 4096 + px];
        float hi = __bfloat162float(__float2bfloat16_rn(v));
        g_xp[(((size_t)t * 16 + b) * 2 + 0) * 4096 + px] = pack_bf(v, 0.f);
        g_xp[(((size_t)t * 16 + b) * 2 + 1) * 4096 + px] = pack_bf(v - hi, 0.f);
    }
}

// Weights -> A-fragment order: [hb][chunk][ ((tap*4+g)*2+s)*128 + lane*4 + r ]
// reg r: m = lane/4 + (r&1)*8 ; pair = lane%4 + ((r>>1)&1)*4
__global__ void repack_w(const float* __restrict__ W, uint32_t* __restrict__ Wp,
                         int HID, int CIN, int NHB, int layer) {
    int total = NHB * NCHUNK * 9216;
    for (int idx = blockIdx.x * blockDim.x + threadIdx.x; idx < total;
         idx += gridDim.x * blockDim.x) {
        int wrd = idx % 9216, rest = idx / 9216;
        int c = rest % NCHUNK, hb = rest / NCHUNK;
        int r = wrd & 3, lane = (wrd >> 2) & 31, sgt = wrd >> 7;
        int s = sgt & 1, g = (sgt >> 1) & 3, t = sgt >> 3;
        int m  = (lane >> 2) + (r & 1) * 8;
        int pr = (lane & 3) + ((r >> 1) & 1) * 4;
        int p  = c * 8 + pr;
        int hid = hb * 16 + m;
        int k0 = -1, k1 = -1;
        if (layer == 0) {
            if (p < 64)       { k0 = 2 * p + 1; k1 = 2 * p + 2; }
            else if (p == 64) { k0 = 0; }
        } else {
            if (p < 64)      { k0 = 2 * p; k1 = 2 * p + 1; }
            else if (p < 70) { k0 = 128 + 2 * (p - 64); k1 = k0 + 1; }
        }
        float w0 = 0.f, w1 = 0.f;
        if (hid < HID) {
            if (k0 >= 0) w0 = W[((size_t)(g * HID + hid) * CIN + k0) * 9 + t];
            if (k1 >= 0) w1 = W[((size_t)(g * HID + hid) * CIN + k1) * 9 + t];
        }
        Wp[idx] = (s == 0) ? pack_bf(w0, w1) : pack_bf(bflo(w0), bflo(w1));
    }
}

// -------------------- fused conv + LSTM step --------------------------------
// Grid (8 y-tiles, NHB, 16 batch), block 512 = 16 warps (wx 0..7, wy 0..1).
// Warp: 16 hid x 4 gates x 32 px (8-px strip, 4 rows). 64 f32 accs/thread.
template <int NPA, int NPB, int HID>
__global__ __launch_bounds__(512, 1)
void conv_step(const uint32_t* __restrict__ actA,   // [b][NPA][2][4096]
               const uint32_t* __restrict__ actB,   // [b][NPB][2][4096]
               const uint32_t* __restrict__ Wg,     // [hb][9][9216]
               const float*    __restrict__ bias,
               float*          __restrict__ cbuf,   // [b][HID][4096]
               uint32_t*       __restrict__ hout,   // [b][HID/2][2][4096]
               float*          __restrict__ hfout) {
    extern __shared__ uint32_t sm[];
    const int tid = threadIdx.x;
    const int lane = tid & 31, warp = tid >> 5;
    const int tg = lane & 3, gq = lane >> 2;
    const int wx = warp & 7, wy = warp >> 3;
    const int y0 = blockIdx.x * 8;
    const int hb = blockIdx.y;
    const int b  = blockIdx.z;
    const uint32_t* wgm = Wg + (size_t)hb * NCHUNK * 9216;

    // zero halo columns (0..3, 68..71) for all planes, both buffers
    for (int u = tid; u < 640; u += 512) {
        int side = u & 1, v = u >> 1;
        int r = v % 10, p = (v / 10) & 7, s = (v / 80) & 1, bfi = v / 160;
        uint32_t* dst = sm + bfi * SW_ACT_BUF + s * SW_ACT_S + p * 728 +
                        r * 72 + (side ? 68 : 0);
        *(uint4*)dst = make_uint4(0, 0, 0, 0);
    }

    float acc[4][4][4];
#pragma unroll
    for (int g = 0; g < 4; g++)
#pragma unroll
        for (int n = 0; n < 4; n++)
#pragma unroll
            for (int r = 0; r < 4; r++) acc[g][n][r] = 0.f;

    auto ldchunk = [&](int c, int bfi) {
#pragma unroll
        for (int k = 0; k < 5; k++) {
            int u = tid + k * 512;               // 2560 uint4: act data
            if (u < 2560) {
                int p = u & 7, s = (u >> 3) & 1, rest = u >> 4;
                int r = rest % 10, seg = rest / 10;     // seg: 16 x 4px
                int pair = c * 8 + p;
                int y = y0 + r - 1;
                uint32_t* dst = sm + bfi * SW_ACT_BUF + s * SW_ACT_S +
                                p * 728 + r * 72 + 4 + seg * 4;
                const uint32_t* src = nullptr;
                if ((unsigned)y < 64u) {
                    if (pair < NPA)
                        src = actA + (((size_t)b * NPA + pair) * 2 + s) * 4096 +
                              y * 64 + seg * 4;
                    else if (pair < NPA + NPB)
                        src = actB + (((size_t)b * NPB + (pair - NPA)) * 2 + s) * 4096 +
                              y * 64 + seg * 4;
                }
                if (src) cpa16(smaddr(dst), src);
                else     *(uint4*)dst = make_uint4(0, 0, 0, 0);
            }
        }
        const uint32_t* wsrc = wgm + (size_t)c * 9216;
        uint32_t* wdst = sm + SW_W_OFF + bfi * SW_W_BUF;
#pragma unroll
        for (int k = 0; k < 5; k++) {
            int u = tid + k * 512;               // 2304 uint4: weights
            if (u < 2304) cpa16(smaddr(wdst + u * 4), wsrc + u * 4);
        }
        asm volatile("cp.async.commit_group;");
    };

    ldchunk(0, 0);

    for (int c = 0; c < NCHUNK; c++) {
        const int bfi = c & 1;
        if (c + 1 < NCHUNK) {
            ldchunk(c + 1, bfi ^ 1);
            asm volatile("cp.async.wait_group 1;");
        } else {
            asm volatile("cp.async.wait_group 0;");
        }
        __syncthreads();

        const uint32_t* ws = sm + SW_W_OFF + bfi * SW_W_BUF;
        const uint32_t* aH = sm + bfi * SW_ACT_BUF;
        const uint32_t* aL = aH + SW_ACT_S;

#pragma unroll
        for (int ky = 0; ky < 3; ky++) {
#pragma unroll
            for (int kx = 0; kx < 3; kx++) {
                const int t = ky * 3 + kx;
                const int cb = 4 + wx * 8 + gq + kx - 1;
                uint32_t bh[4][2], bl[4][2];
#pragma unroll
                for (int nt = 0; nt < 4; nt++) {
                    int o0 = tg * 728 + (wy * 4 + ky + nt) * 72 + cb;
                    bh[nt][0] = aH[o0]; bh[nt][1] = aH[o0 + 4 * 728];
                    bl[nt][0] = aL[o0]; bl[nt][1] = aL[o0 + 4 * 728];
                }
#pragma unroll
                for (int g = 0; g < 4; g++) {
                    uint4 ah = *(const uint4*)(ws + ((t * 4 + g) * 2 + 0) * 128 + lane * 4);
                    uint4 al = *(const uint4*)(ws + ((t * 4 + g) * 2 + 1) * 128 + lane * 4);
#pragma unroll
                    for (int nt = 0; nt < 4; nt++) {
                        mma_bf16(acc[g][nt], (const uint32_t*)&ah, bh[nt][0], bh[nt][1]);
                        mma_bf16(acc[g][nt], (const uint32_t*)&ah, bl[nt][0], bl[nt][1]);
                        mma_bf16(acc[g][nt], (const uint32_t*)&al, bh[nt][0], bh[nt][1]);
                    }
                }
            }
        }
        __syncthreads();
    }

    // ---- LSTM epilogue -----------------------------------------------------
    const int xpx = wx * 8 + tg * 2;
#pragma unroll
    for (int part = 0; part < 2; part++) {
        const int hid = hb * 16 + gq + part * 8;
        const bool hv = (hid < HID);
        float bi = 0.f, bfv = 0.f, bo = 0.f, bg = 0.f;
        if (hv) {
            bi = bias[hid]; bfv = bias[HID + hid];
            bo = bias[2 * HID + hid]; bg = bias[3 * HID + hid];
        }
#pragma unroll
        for (int nt = 0; nt < 4; nt++) {
            const int y = y0 + wy * 4 + nt;
            const size_t coff =
                ((size_t)(b * HID + (hv ? hid : 0))) * 4096 + (size_t)y * 64 + xpx;
            float2 c2 = hv ? *(const float2*)(cbuf + coff) : make_float2(0.f, 0.f);
            float cold[2] = {c2.x, c2.y}, hn[2];
#pragma unroll
            for (int q = 0; q < 2; q++) {
                float I = sigf(acc[0][nt][part * 2 + q] + bi);
                float F = sigf(acc[1][nt][part * 2 + q] + bfv);
                float O = sigf(acc[2][nt][part * 2 + q] + bo);
                float G = tanhf(acc[3][nt][part * 2 + q] + bg);
                float cn = F * cold[q] + I * G;
                cold[q] = cn;
                hn[q] = O * tanhf(cn);
            }
            if (hv) {
                *(float2*)(cbuf + coff) = make_float2(cold[0], cold[1]);
                if (hfout)
                    *(float2*)(hfout + coff) = make_float2(hn[0], hn[1]);
            }
            // pack channel pairs: partner hid^1 lives at lane^4
            float pn0 = __shfl_xor_sync(0xffffffffu, hn[0], 4);
            float pn1 = __shfl_xor_sync(0xffffffffu, hn[1], 4);
            if (((gq & 1) == 0) && hv) {
                const int qp = hid >> 1;
                const size_t ob =
                    (((size_t)b * (HID / 2) + qp) * 2) * 4096 + (size_t)y * 64 + xpx;
                *(uint2*)(hout + ob) = make_uint2(pack_bf(hn[0], pn0), pack_bf(hn[1], pn1));
                *(uint2*)(hout + ob + 4096) =
                    make_uint2(pack_bf(bflo(hn[0]), bflo(pn0)),
                               pack_bf(bflo(hn[1]), bflo(pn1)));
            }
        }
    }
}

// -------------------- host driver -------------------------------------------
extern "C" void kernel_launch(void* const* d_in, const int* in_sizes, int n_in,
                              void* d_out, int out_size) {
    (void)in_sizes; (void)n_in; (void)out_size;
    const float* history = (const float*)d_in[0];
    const float* W0 = (const float*)d_in[2];
    const float* b0 = (const float*)d_in[3];
    const float* W1 = (const float*)d_in[4];
    const float* b1 = (const float*)d_in[5];

    uint32_t *h0p, *h1p, *xp, *wp0, *wp1;
    float *c0, *c1, *h1f;
    cudaGetSymbolAddress((void**)&h0p, g_h0p);
    cudaGetSymbolAddress((void**)&h1p, g_h1p);
    cudaGetSymbolAddress((void**)&xp,  g_xp);
    cudaGetSymbolAddress((void**)&wp0, g_wp0);
    cudaGetSymbolAddress((void**)&wp1, g_wp1);
    cudaGetSymbolAddress((void**)&c0,  g_c0);
    cudaGetSymbolAddress((void**)&c1,  g_c1);
    cudaGetSymbolAddress((void**)&h1f, g_h1f);

    cudaFuncSetAttribute(conv_step<64, 1, 128>,
                         cudaFuncAttributeMaxDynamicSharedMemorySize, SMEM_BYTES);
    cudaFuncSetAttribute(conv_step<64, 6, 12>,
                         cudaFuncAttributeMaxDynamicSharedMemorySize, SMEM_BYTES);

    zero_init_kernel<<<1024, 256>>>();
    xprep_kernel<<<768, 256>>>(history);
    repack_w<<<648, 256>>>(W0, wp0, 128, 129, 8, 0);
    repack_w<<<81, 256>>>(W1, wp1, 12, 140, 1, 1);

    const size_t H0SZ = (size_t)16 * 64 * 2 * 4096;
    const size_t H1SZ = (size_t)16 * 6 * 2 * 4096;

    int pa = 0;
    for (int t = 0; t < TSTEPS; t++) {
        const uint32_t* h0r = h0p + (size_t)pa * H0SZ;
        uint32_t*       h0w = h0p + (size_t)(1 - pa) * H0SZ;
        const uint32_t* h1r = h1p + (size_t)pa * H1SZ;
        uint32_t*       h1w = h1p + (size_t)(1 - pa) * H1SZ;

        conv_step<64, 1, 128><<<dim3(8, 8, 16), 512, SMEM_BYTES>>>(
            h0r, xp + (size_t)t * 16 * 2 * 4096, wp0, b0, c0, h0w, nullptr);

        conv_step<64, 6, 12><<<dim3(8, 1, 16), 512, SMEM_BYTES>>>(
            h0w, h1r, wp1, b1, c1, h1w, h1f);

        pa ^= 1;
    }

    cudaMemcpyAsync(d_out, h1f, (size_t)16 * 12 * 4096 * sizeof(float),
                    cudaMemcpyDeviceToDevice);
}